// round 17
// baseline (speedup 1.0000x reference)
#include <cuda_runtime.h>
#include <cuda_bf16.h>
#include <cstdint>

// Problem constants (fixed by setup_inputs)
#define B_   8
#define NS   5
#define NQ   128
#define T_   16
#define D_   2048
#define NROWS (B_*NQ)           // 1024

__device__ float g_rowterm[NROWS];
__device__ unsigned int g_done;   // zero-init; last block resets

// softmin with fused exp2/log2 constants: C1 = 1/(lam*ln2), C2 = lam*ln2
#define C1 14.426950408889634f
#define C2 0.06931471805599453f

__device__ __forceinline__ float ex2f(float x) {
    float r; asm("ex2.approx.f32 %0, %1;" : "=f"(r) : "f"(x)); return r;
}
__device__ __forceinline__ float lg2f(float x) {
    float r; asm("lg2.approx.f32 %0, %1;" : "=f"(r) : "f"(x)); return r;
}
__device__ __forceinline__ float softmin2(float a, float b) {
    float mn = fminf(a, b);
    float e = ex2f(-fabsf(a - b) * C1);
    return fmaf(-C2, lg2f(1.0f + e), mn);
}
__device__ __forceinline__ float softmin3(float a, float b, float c) {
    float mn = fminf(fminf(a, b), c);
    float s = ex2f((mn - a) * C1) + ex2f((mn - b) * C1) + ex2f((mn - c) * C1);
    return fmaf(-C2, lg2f(s), mn);
}

__device__ __forceinline__ uint32_t smem_u32(const void* p) {
    uint32_t a;
    asm("{ .reg .u64 t; cvta.to.shared.u64 t, %1; cvt.u32.u64 %0, t; }" : "=r"(a) : "l"(p));
    return a;
}
__device__ __forceinline__ void ldsm4(uint32_t addr, uint32_t& r0, uint32_t& r1,
                                      uint32_t& r2, uint32_t& r3) {
    asm volatile("ldmatrix.sync.aligned.m8n8.x4.shared.b16 {%0,%1,%2,%3}, [%4];"
                 : "=r"(r0), "=r"(r1), "=r"(r2), "=r"(r3) : "r"(addr));
}
// f32x4 -> packed e4m3x4 (one u32, byte k-order x,y,z,w)
__device__ __forceinline__ uint32_t cvt_e4(float4 v) {
    uint16_t lo, hi;
    asm("cvt.rn.satfinite.e4m3x2.f32 %0, %1, %2;" : "=h"(lo) : "f"(v.y), "f"(v.x));
    asm("cvt.rn.satfinite.e4m3x2.f32 %0, %1, %2;" : "=h"(hi) : "f"(v.w), "f"(v.z));
    uint32_t r;
    asm("mov.b32 %0, {%1, %2};" : "=r"(r) : "h"(lo), "h"(hi));
    return r;
}

// ---------------- fused kernel: FP8 GEMM (split-K x2) -> cosine dist -> soft-DTW -> CE ----------------
#define BM 80
#define BN 128
#define BK 32
#define GT 640        // 20 warps: 2 K-groups x (5 M x 2 N)
#define PSTRIDE 260   // 16B-aligned problem stride

#define STRIDE  48                // fp8 tile row stride (32B data + 16B pad)
#define STAGE_B (208*STRIDE)      // 9984 (A rows 0..79, B rows 80..207)
#define BOFF    (80*STRIDE)       // 3840
#define KG_B    (4*STAGE_B)       // 39936 per K-group (4 stages)
#define OFF_ACC (2*KG_B)          // 79872

#define ACCBUF_F 10560
#define SMEM_BYTES (OFF_ACC + ACCBUF_F*4 + (256+160+80)*4)

__global__ __launch_bounds__(GT, 1) void gemm_dtw_kernel(
        const float* __restrict__ supp, const float* __restrict__ query,
        const int* __restrict__ ys, float* __restrict__ out) {
    extern __shared__ char smc[];
    float* accbuf = (float*)(smc + OFF_ACC);                  // 10560 f32 (later sDist)
    float* sDist  = accbuf;
    float* qsum   = accbuf + ACCBUF_F;                        // [2][128]
    float* ssum   = qsum + 256;                               // [2][80]
    float* t1s    = ssum + 160;                               // [40]
    float* t2s    = t1s + 40;                                 // [40]

    const int b = blockIdx.y, nt = blockIdx.x;
    const int tid = threadIdx.x, wid = tid >> 5, lane = tid & 31;
    const int kg = wid >= 10;            // K-split group
    const int gtid = tid - kg * 320;
    const int gwid = wid - kg * 10;
    const float* Ag = supp  + (size_t)b * BM * D_;
    const float* Bg = query + ((size_t)b * (NQ*T_) + (size_t)nt * BN) * D_;

    float acc[8][4];
    #pragma unroll
    for (int j = 0; j < 8; j++) { acc[j][0]=0.f; acc[j][1]=0.f; acc[j][2]=0.f; acc[j][3]=0.f; }

    const int wm = gwid % 5;             // M warp tile (16 rows)
    const int wn = gwid / 5;             // N warp tile (64 cols)
    const int g  = lane >> 2, t = lane & 3;
    const int quad = lane >> 3, qi = lane & 7;

    const uint32_t smb = smem_u32(smc);
    const uint32_t smbG = smb + kg * KG_B;
    char* const scG = smc + kg * KG_B;

    // ---- fp8 ldsm offsets within a stage (verified m16n8k32 fragment layouts) ----
    const uint32_t offA = (uint32_t)((wm*16 + (quad & 1)*8 + qi) * STRIDE + (quad >> 1) * 16);
    uint32_t offB[4];
    #pragma unroll
    for (int jj = 0; jj < 4; jj++)
        offB[jj] = (uint32_t)(BOFF + (wn*64 + (2*jj + (quad >> 1))*8 + qi) * STRIDE + (quad & 1) * 16);

    // per-group loader coordinates (each row covered by one aligned 8-lane group)
    const int ar0 = gtid >> 3,        ac0 = (gtid & 7) * 4;
    const int ar1 = (gtid+320) >> 3,  ac1 = ((gtid+320) & 7) * 4;
    const int br0 = gtid >> 3,        bc0 = (gtid & 7) * 4;
    const int br1 = (gtid+320) >> 3,  bc1 = ((gtid+320) & 7) * 4;
    const int br2 = (gtid+640) >> 3,  bc2 = ((gtid+640) & 7) * 4;
    const int br3 = (gtid+960) >> 3,  bc3 = ((gtid+960) & 7) * 4;
    const bool b3ok = (gtid + 960) < BN * 8;

    float4 ra0, ra1, rb0, rb1, rb2, rb3;
    rb3.x = rb3.y = rb3.z = rb3.w = 0.f;

    float as0 = 0.f, as1 = 0.f, qs0 = 0.f, qs1 = 0.f, qs2 = 0.f, qs3 = 0.f;
    #define DOT4(v) ((v).x*(v).x + (v).y*(v).y + (v).z*(v).z + (v).w*(v).w)

    // supp: default caching (L2-resident reuse); query: streaming evict-first
    #define LDG_CHUNK(k0) do { \
        ra0 = *(const float4*)(Ag + (size_t)ar0*D_ + (k0) + ac0); \
        ra1 = *(const float4*)(Ag + (size_t)ar1*D_ + (k0) + ac1); \
        rb0 = __ldcs((const float4*)(Bg + (size_t)br0*D_ + (k0) + bc0)); \
        rb1 = __ldcs((const float4*)(Bg + (size_t)br1*D_ + (k0) + bc1)); \
        rb2 = __ldcs((const float4*)(Bg + (size_t)br2*D_ + (k0) + bc2)); \
        if (b3ok) rb3 = __ldcs((const float4*)(Bg + (size_t)br3*D_ + (k0) + bc3)); } while(0)

    #define SUMSQ_CHUNK() do { \
        as0 += DOT4(ra0); as1 += DOT4(ra1); \
        qs0 += DOT4(rb0); qs1 += DOT4(rb1); qs2 += DOT4(rb2); qs3 += DOT4(rb3); } while(0)

    // fp8 store: f32 col index == byte offset (1B/elem)
    #define STS_CHUNK(stg) do { \
        char* bs = scG + (stg) * STAGE_B; \
        *(uint32_t*)(bs + ar0*STRIDE + ac0) = cvt_e4(ra0); \
        *(uint32_t*)(bs + ar1*STRIDE + ac1) = cvt_e4(ra1); \
        *(uint32_t*)(bs + BOFF + br0*STRIDE + bc0) = cvt_e4(rb0); \
        *(uint32_t*)(bs + BOFF + br1*STRIDE + bc1) = cvt_e4(rb1); \
        *(uint32_t*)(bs + BOFF + br2*STRIDE + bc2) = cvt_e4(rb2); \
        if (b3ok) *(uint32_t*)(bs + BOFF + br3*STRIDE + bc3) = cvt_e4(rb3); } while(0)

    #define MMA_SECTION(stg) do { \
        const uint32_t base = smbG + (uint32_t)(stg) * STAGE_B; \
        uint32_t a0, a1, a2, a3; \
        ldsm4(base + offA, a0, a1, a2, a3); \
        uint32_t bf[16]; \
        _Pragma("unroll") \
        for (int jj = 0; jj < 4; jj++) \
            ldsm4(base + offB[jj], bf[4*jj], bf[4*jj+1], bf[4*jj+2], bf[4*jj+3]); \
        _Pragma("unroll") \
        for (int j = 0; j < 8; j++) { \
            asm volatile( \
                "mma.sync.aligned.m16n8k32.row.col.f32.e4m3.e4m3.f32 " \
                "{%0,%1,%2,%3}, {%4,%5,%6,%7}, {%8,%9}, {%0,%1,%2,%3};\n" \
                : "+f"(acc[j][0]), "+f"(acc[j][1]), "+f"(acc[j][2]), "+f"(acc[j][3]) \
                : "r"(a0), "r"(a1), "r"(a2), "r"(a3), "r"(bf[2*j]), "r"(bf[2*j+1])); \
        } } while(0)

    #define GBAR() asm volatile("bar.sync %0, %1;" :: "r"(kg + 1), "r"(320) : "memory")

    // group chunk c (0..31) sits at global K offset (kg + 2c)*BK

    // ---- prologue: chunks 0,1 staged; chunk 2 in regs ----
    LDG_CHUNK(kg * BK);
    SUMSQ_CHUNK();
    STS_CHUNK(0);
    LDG_CHUNK((kg + 2) * BK);
    SUMSQ_CHUNK();
    STS_CHUNK(1);
    LDG_CHUNK((kg + 4) * BK);
    GBAR();

    // ---- mainloop: 16 double-chunk iterations, one barrier each ----
    #pragma unroll 1
    for (int i = 0; i < 16; i++) {
        if (i < 15) {                     // stage chunk 2i+2 (regs from prev iter)
            SUMSQ_CHUNK();
            STS_CHUNK((2*i + 2) & 3);
            LDG_CHUNK((kg + 2*(2*i + 3)) * BK);
        }
        MMA_SECTION((2*i) & 3);
        if (i < 15) {                     // stage chunk 2i+3 (regs from this iter)
            SUMSQ_CHUNK();
            STS_CHUNK((2*i + 3) & 3);
        }
        if (i < 14) LDG_CHUNK((kg + 2*(2*i + 4)) * BK);
        MMA_SECTION((2*i + 1) & 3);
        GBAR();
    }

    // ---- per-group deterministic 8-lane reduction of sum-of-squares ----
    #pragma unroll
    for (int o = 4; o; o >>= 1) {
        as0 += __shfl_xor_sync(0xffffffffu, as0, o);
        as1 += __shfl_xor_sync(0xffffffffu, as1, o);
        qs0 += __shfl_xor_sync(0xffffffffu, qs0, o);
        qs1 += __shfl_xor_sync(0xffffffffu, qs1, o);
        qs2 += __shfl_xor_sync(0xffffffffu, qs2, o);
        qs3 += __shfl_xor_sync(0xffffffffu, qs3, o);
    }
    if ((gtid & 7) == 0) {
        ssum[kg*80 + ar0] = as0; ssum[kg*80 + ar1] = as1;
        qsum[kg*128 + br0] = qs0; qsum[kg*128 + br1] = qs1; qsum[kg*128 + br2] = qs2;
        if (b3ok) qsum[kg*128 + br3] = qs3;
    }

    // ---- kg=1 dumps acc (stride-33 conflict-free layout) ----
    if (kg == 1) {
        float* ab = accbuf + gwid * 1056 + lane;
        #pragma unroll
        for (int j = 0; j < 8; j++)
            #pragma unroll
            for (int c = 0; c < 4; c++)
                ab[(j*4 + c) * 33] = acc[j][c];
    }
    __syncthreads();

    // ---- kg=0: reduce + combine norms ----
    if (kg == 0) {
        const float* ab = accbuf + gwid * 1056 + lane;
        #pragma unroll
        for (int j = 0; j < 8; j++)
            #pragma unroll
            for (int c = 0; c < 4; c++)
                acc[j][c] += ab[(j*4 + c) * 33];
    }
    if (tid < BN)            qsum[tid] = rsqrtf(fmaxf(qsum[tid] + qsum[128 + tid], 1e-12f));
    else if (tid < BN + BM)  ssum[tid - BN] = rsqrtf(fmaxf(ssum[tid - BN] + ssum[80 + tid - BN], 1e-12f));
    __syncthreads();

    // ---- epilogue: dist into smem (kg=0 only) ----
    if (kg == 0) {
        #pragma unroll
        for (int j = 0; j < 8; j++) {
            const int lc = wn * 64 + j * 8 + t * 2;
            #pragma unroll
            for (int half = 0; half < 2; half++) {
                const int lr = wm * 16 + g + half * 8;      // 0..79
                const float invs = ssum[lr];
                const int s = lr >> 4, l = lr & 15;
                #pragma unroll
                for (int e = 0; e < 2; e++) {
                    const int c = lc + e;                    // local col 0..127
                    const int qloc = c >> 4, m = c & 15;
                    const int pb = qloc * NS + s;            // 0..39
                    const float v = acc[j][half * 2 + e];
                    sDist[pb * PSTRIDE + (l << 4) + m] = 1.0f - v * invs * qsum[c];
                }
            }
        }
    }
    __syncthreads();

    // ---- soft-DTW: anti-diagonal wavefront, 8 lanes per (problem, direction) ----
    {
        const int j = tid & 7, u = tid >> 3;
        const int pb = u >> 1, dir = u & 1;
        const float* dm = sDist + pb * PSTRIDE;
        const int base = dir ? 255 : 0;
        const int sgn = dir ? -1 : 1;
        #define EL(l, mm) dm[base + sgn * (16*(l) + (mm))]

        // row 0: 8-lane inclusive scan of pair sums
        float d0a = EL(0, 2*j), d0b = EL(0, 2*j + 1);
        const float pairs = d0a + d0b;
        float pre = pairs;
        #pragma unroll
        for (int o = 1; o < 8; o <<= 1) {
            float v = __shfl_up_sync(0xffffffffu, pre, o, 8);
            if (j >= o) pre += v;
        }
        float cur1 = pre - d0b;    // opt[0][2j+1]
        float cur2 = pre;          // opt[0][2j+2]
        float cur3 = pre;          // lane 7: opt[0][17]
        float old2 = cur2;

        #pragma unroll 1
        for (int s = 1; s <= 22; s++) {
            const float nl = __shfl_up_sync(0xffffffffu, cur2, 1, 8);  // opt[l][2j]
            const float nd = __shfl_up_sync(0xffffffffu, old2, 1, 8);  // opt[l-1][2j]
            const int l = s - j;
            if (l >= 1 && l <= 15) {
                float v1;
                if (j == 0) v1 = softmin3(0.f, 0.f, cur1) + EL(l, 0);
                else        v1 = softmin2(nd, nl) + EL(l, 2*j);
                const float v2 = softmin2(cur1, v1) + EL(l, 2*j + 1);
                if (j == 7) cur3 = softmin3(cur2, v2, cur3);   // m=17 boundary, d=0
                old2 = cur2;
                cur1 = v1;
                cur2 = v2;
            }
        }
        if (j == 7) {
            if (dir == 0) t1s[pb] = cur3;
            else          t2s[pb] = cur3;
        }
        #undef EL
    }
    __syncthreads();

    // ---- per-block outputs: tam + per-query CE term ----
    if (tid < 40) {
        const int qloc = tid / NS, s = tid % NS;
        const int row = b * NQ + nt * 8 + qloc;
        out[1 + row * NS + s] = 0.5f * (t1s[tid] + t2s[tid]);
    }
    if (tid < 8) {
        const int row = b * NQ + nt * 8 + tid;
        float t1[NS], t2[NS];
        #pragma unroll
        for (int s = 0; s < NS; s++) { t1[s] = t1s[tid * NS + s]; t2[s] = t2s[tid * NS + s]; }
        float mx1 = -t1[0], mx2 = -t2[0];
        #pragma unroll
        for (int s = 1; s < NS; s++) { mx1 = fmaxf(mx1, -t1[s]); mx2 = fmaxf(mx2, -t2[s]); }
        float se1 = 0.f, se2 = 0.f;
        #pragma unroll
        for (int s = 0; s < NS; s++) { se1 += __expf(-t1[s] - mx1); se2 += __expf(-t2[s] - mx2); }
        const int y = ys[row];
        g_rowterm[row] = (mx1 + __logf(se1) + t1[y]) + (mx2 + __logf(se2) + t2[y]);
    }

    // ---- last block computes the final loss ----
    __shared__ unsigned s_last;
    __shared__ float s_red[20];
    __threadfence();
    __syncthreads();
    if (tid == 0) s_last = (atomicAdd(&g_done, 1u) == 127u) ? 1u : 0u;
    __syncthreads();
    if (s_last) {
        float v = 0.f;
        if (tid < 512) v = g_rowterm[tid] + g_rowterm[tid + 512];
        #pragma unroll
        for (int o = 16; o; o >>= 1) v += __shfl_xor_sync(0xffffffffu, v, o);
        if (lane == 0 && wid < 16) s_red[wid] = v;
        __syncthreads();
        if (wid == 0) {
            float u = (lane < 16) ? s_red[lane] : 0.f;
            #pragma unroll
            for (int o = 8; o; o >>= 1) u += __shfl_xor_sync(0xffffffffu, u, o);
            if (lane == 0) { out[0] = 0.5f * u / (float)NROWS; g_done = 0u; }
        }
    }
}

// ---------------- launch ----------------
extern "C" void kernel_launch(void* const* d_in, const int* in_sizes, int n_in,
                              void* d_out, int out_size) {
    const float* supp  = (const float*)d_in[0];
    const float* query = (const float*)d_in[1];
    const int*   ys    = (const int*)d_in[2];
    float* out = (float*)d_out;

    static bool attr_set = false;
    if (!attr_set) {
        cudaFuncSetAttribute(gemm_dtw_kernel,
                             cudaFuncAttributeMaxDynamicSharedMemorySize, SMEM_BYTES);
        attr_set = true;
    }

    gemm_dtw_kernel<<<dim3(16, B_), GT, SMEM_BYTES>>>(supp, query, ys, out);
}